// round 1
// baseline (speedup 1.0000x reference)
#include <cuda_runtime.h>
#include <math.h>

#define EMB    1024
#define S_LEN  2048
#define BATCH  4
#define NH     16
#define HD     64
#define M_TOTAL (BATCH * S_LEN)   // 8192

// ---- scratch (static device globals; no allocations allowed) ----
__device__ float g_Q[(size_t)M_TOTAL * EMB];
__device__ float g_K[(size_t)M_TOTAL * EMB];
__device__ float g_V[(size_t)M_TOTAL * EMB];
__device__ float g_O[(size_t)M_TOTAL * EMB];

// ============================================================================
// SGEMM + bias:  C[M,1024] = A[M,1024] @ W[1024,1024] + bias
// 128x128 block tile, BK=8, 256 threads, 8x8 per thread, reg-staged prefetch.
// ============================================================================
__global__ __launch_bounds__(256, 2)
void sgemm_bias(const float* __restrict__ A, const float* __restrict__ W,
                const float* __restrict__ bias, float* __restrict__ C) {
    __shared__ float As[8][128];
    __shared__ float Bs[8][128];

    const int tid = threadIdx.x;
    const int tx = tid & 15;
    const int ty = tid >> 4;
    const int rowBase = blockIdx.y * 128;
    const int colBase = blockIdx.x * 128;

    // A tile load mapping: 128 rows x 8 k, one float4 per thread
    const int arow = tid >> 1;          // 0..127
    const int ak4  = (tid & 1) << 2;    // 0 or 4
    // B tile load mapping: 8 rows x 128 cols, one float4 per thread
    const int brow = tid >> 5;          // 0..7
    const int bc4  = (tid & 31) << 2;   // 0..124

    const float* Aptr = A + (size_t)(rowBase + arow) * EMB + ak4;
    const float* Wptr = W + (size_t)brow * EMB + colBase + bc4;

    float acc[8][8];
    #pragma unroll
    for (int i = 0; i < 8; ++i)
        #pragma unroll
        for (int j = 0; j < 8; ++j) acc[i][j] = 0.0f;

    float4 aReg = *(const float4*)(Aptr);
    float4 bReg = *(const float4*)(Wptr);

    const int NKT = EMB / 8;
    for (int kt = 0; kt < NKT; ++kt) {
        // commit staged tile to smem (A transposed k-major)
        As[ak4 + 0][arow] = aReg.x;
        As[ak4 + 1][arow] = aReg.y;
        As[ak4 + 2][arow] = aReg.z;
        As[ak4 + 3][arow] = aReg.w;
        *(float4*)&Bs[brow][bc4] = bReg;
        __syncthreads();

        if (kt + 1 < NKT) {
            aReg = *(const float4*)(Aptr + (kt + 1) * 8);
            bReg = *(const float4*)(Wptr + (size_t)(kt + 1) * 8 * EMB);
        }

        #pragma unroll
        for (int kk = 0; kk < 8; ++kk) {
            float a[8], b[8];
            *(float4*)&a[0] = *(const float4*)&As[kk][ty * 8];
            *(float4*)&a[4] = *(const float4*)&As[kk][ty * 8 + 4];
            *(float4*)&b[0] = *(const float4*)&Bs[kk][tx * 8];
            *(float4*)&b[4] = *(const float4*)&Bs[kk][tx * 8 + 4];
            #pragma unroll
            for (int i = 0; i < 8; ++i)
                #pragma unroll
                for (int j = 0; j < 8; ++j)
                    acc[i][j] = fmaf(a[i], b[j], acc[i][j]);
        }
        __syncthreads();
    }

    // epilogue: add bias, store float4
    #pragma unroll
    for (int i = 0; i < 8; ++i) {
        const int row = rowBase + ty * 8 + i;
        #pragma unroll
        for (int j4 = 0; j4 < 8; j4 += 4) {
            const int col = colBase + tx * 8 + j4;
            float4 bs = *(const float4*)&bias[col];
            float4 o;
            o.x = acc[i][j4 + 0] + bs.x;
            o.y = acc[i][j4 + 1] + bs.y;
            o.z = acc[i][j4 + 2] + bs.z;
            o.w = acc[i][j4 + 3] + bs.w;
            *(float4*)&C[(size_t)row * EMB + col] = o;
        }
    }
}

// ============================================================================
// Flash attention, fp32. One block per (b, h, 64-row q tile). 256 threads.
// Q/K/V in [B,S,E] layout, head h occupies cols [h*64, h*64+64).
// smem: Qs[64][64] | KT[64][65] (aliased by Ps[64][64]) | Vs[64][64]
// ============================================================================
#define KT_STR 65
#define ATTN_SMEM_FLOATS (64*64 + 64*KT_STR + 64*64)
#define ATTN_SMEM_BYTES  (ATTN_SMEM_FLOATS * 4)

__global__ __launch_bounds__(256, 2)
void attn_kernel(const float* __restrict__ Q, const float* __restrict__ K,
                 const float* __restrict__ V, float* __restrict__ O) {
    extern __shared__ float sm[];
    float* Qs = sm;                      // [64][64]
    float* KT = sm + 64 * 64;            // [64][65], d-major (KT[d][kv])
    float* Ps = KT;                      // alias, [64][64]
    float* Vs = sm + 64 * 64 + 64 * KT_STR;  // [64][64]

    const int tid = threadIdx.x;
    const int tx  = tid & 15;
    const int ty  = tid >> 4;
    const int ty4 = ty * 4;
    const int tx4 = tx * 4;

    const int bh = blockIdx.y;             // 0..63
    const int b  = bh >> 4;
    const int h  = bh & 15;
    const int qbase = blockIdx.x * 64;

    const float* Qg = Q + (size_t)b * S_LEN * EMB + h * HD;
    const float* Kg = K + (size_t)b * S_LEN * EMB + h * HD;
    const float* Vg = V + (size_t)b * S_LEN * EMB + h * HD;

    // tile-load mapping: thread owns rows lr, lr+16, lr+32, lr+48; cols lc4..lc4+3
    const int lr  = tid >> 4;           // 0..15
    const int lc4 = (tid & 15) << 2;    // 0..60

    // load Q tile (row-major)
    #pragma unroll
    for (int u = 0; u < 4; ++u) {
        const int r = lr + u * 16;
        float4 v = *(const float4*)(Qg + (size_t)(qbase + r) * EMB + lc4);
        *(float4*)&Qs[r * 64 + lc4] = v;
    }

    float m_i[4], l_i[4], acc[4][4];
    #pragma unroll
    for (int i = 0; i < 4; ++i) {
        m_i[i] = -INFINITY;
        l_i[i] = 0.0f;
        #pragma unroll
        for (int j = 0; j < 4; ++j) acc[i][j] = 0.0f;
    }

    // stage K tile 0
    float4 kreg[4];
    #pragma unroll
    for (int u = 0; u < 4; ++u)
        kreg[u] = *(const float4*)(Kg + (size_t)(lr + u * 16) * EMB + lc4);

    __syncthreads();  // Qs visible

    const int NT = S_LEN / 64;
    for (int t = 0; t < NT; ++t) {
        // commit K tile transposed: KT[d][kv]
        #pragma unroll
        for (int u = 0; u < 4; ++u) {
            const int kv = lr + u * 16;
            KT[(lc4 + 0) * KT_STR + kv] = kreg[u].x;
            KT[(lc4 + 1) * KT_STR + kv] = kreg[u].y;
            KT[(lc4 + 2) * KT_STR + kv] = kreg[u].z;
            KT[(lc4 + 3) * KT_STR + kv] = kreg[u].w;
        }
        __syncthreads();

        // prefetch V tile t (consumed after next barrier)
        float4 vreg[4];
        #pragma unroll
        for (int u = 0; u < 4; ++u)
            vreg[u] = *(const float4*)(Vg + (size_t)(t * 64 + lr + u * 16) * EMB + lc4);

        // S = Q @ K^T * scale  (4x4 per thread)
        float s[4][4];
        #pragma unroll
        for (int i = 0; i < 4; ++i)
            #pragma unroll
            for (int j = 0; j < 4; ++j) s[i][j] = 0.0f;

        for (int k = 0; k < 64; k += 4) {
            float aq[4][4];
            #pragma unroll
            for (int i = 0; i < 4; ++i)
                *(float4*)&aq[i][0] = *(const float4*)&Qs[(ty4 + i) * 64 + k];
            #pragma unroll
            for (int kk = 0; kk < 4; ++kk) {
                float bb[4];
                #pragma unroll
                for (int j = 0; j < 4; ++j)
                    bb[j] = KT[(k + kk) * KT_STR + tx4 + j];
                #pragma unroll
                for (int i = 0; i < 4; ++i)
                    #pragma unroll
                    for (int j = 0; j < 4; ++j)
                        s[i][j] = fmaf(aq[i][kk], bb[j], s[i][j]);
            }
        }
        #pragma unroll
        for (int i = 0; i < 4; ++i)
            #pragma unroll
            for (int j = 0; j < 4; ++j) s[i][j] *= 0.125f;  // 1/sqrt(64)

        // row max across 16 tx lanes
        float mt[4];
        #pragma unroll
        for (int i = 0; i < 4; ++i) {
            mt[i] = fmaxf(fmaxf(s[i][0], s[i][1]), fmaxf(s[i][2], s[i][3]));
            #pragma unroll
            for (int off = 8; off > 0; off >>= 1)
                mt[i] = fmaxf(mt[i], __shfl_xor_sync(0xffffffffu, mt[i], off));
        }

        float rs[4], corr[4];
        #pragma unroll
        for (int i = 0; i < 4; ++i) {
            const float mnew = fmaxf(m_i[i], mt[i]);
            corr[i] = __expf(m_i[i] - mnew);
            m_i[i] = mnew;
            float r = 0.0f;
            #pragma unroll
            for (int j = 0; j < 4; ++j) {
                s[i][j] = __expf(s[i][j] - mnew);
                r += s[i][j];
            }
            rs[i] = r;
        }
        #pragma unroll
        for (int i = 0; i < 4; ++i) {
            #pragma unroll
            for (int off = 8; off > 0; off >>= 1)
                rs[i] += __shfl_xor_sync(0xffffffffu, rs[i], off);
            l_i[i] = l_i[i] * corr[i] + rs[i];
            #pragma unroll
            for (int j = 0; j < 4; ++j) acc[i][j] *= corr[i];
        }

        __syncthreads();  // done reading KT -> safe to overwrite with Ps

        // commit P (overwrites KT region) and V tile
        #pragma unroll
        for (int i = 0; i < 4; ++i) {
            float4 p4;
            p4.x = s[i][0]; p4.y = s[i][1]; p4.z = s[i][2]; p4.w = s[i][3];
            *(float4*)&Ps[(ty4 + i) * 64 + tx4] = p4;
        }
        #pragma unroll
        for (int u = 0; u < 4; ++u)
            *(float4*)&Vs[(lr + u * 16) * 64 + lc4] = vreg[u];

        // prefetch K tile t+1 (consumed after PV + barrier)
        if (t + 1 < NT) {
            #pragma unroll
            for (int u = 0; u < 4; ++u)
                kreg[u] = *(const float4*)(Kg + (size_t)((t + 1) * 64 + lr + u * 16) * EMB + lc4);
        }
        __syncthreads();

        // acc += P @ V
        for (int kv = 0; kv < 64; kv += 4) {
            float pq[4][4];
            #pragma unroll
            for (int i = 0; i < 4; ++i)
                *(float4*)&pq[i][0] = *(const float4*)&Ps[(ty4 + i) * 64 + kv];
            #pragma unroll
            for (int u = 0; u < 4; ++u) {
                float4 vv = *(const float4*)&Vs[(kv + u) * 64 + tx4];
                #pragma unroll
                for (int i = 0; i < 4; ++i) {
                    acc[i][0] = fmaf(pq[i][u], vv.x, acc[i][0]);
                    acc[i][1] = fmaf(pq[i][u], vv.y, acc[i][1]);
                    acc[i][2] = fmaf(pq[i][u], vv.z, acc[i][2]);
                    acc[i][3] = fmaf(pq[i][u], vv.w, acc[i][3]);
                }
            }
        }
        __syncthreads();  // done reading Ps/Vs before next tile overwrites
    }

    // epilogue: normalize, write O in [B,S,E] (merged-head) layout
    #pragma unroll
    for (int i = 0; i < 4; ++i) {
        const float inv = 1.0f / l_i[i];
        const int row = qbase + ty4 + i;
        float4 o;
        o.x = acc[i][0] * inv;
        o.y = acc[i][1] * inv;
        o.z = acc[i][2] * inv;
        o.w = acc[i][3] * inv;
        *(float4*)&g_O[(size_t)(b * S_LEN + row) * EMB + h * HD + tx4] = o;
    }
}

// ============================================================================
// launch
// ============================================================================
extern "C" void kernel_launch(void* const* d_in, const int* in_sizes, int n_in,
                              void* d_out, int out_size) {
    const float* x  = (const float*)d_in[0];
    const float* Wq = (const float*)d_in[1];
    const float* bq = (const float*)d_in[2];
    const float* Wk = (const float*)d_in[3];
    const float* bk = (const float*)d_in[4];
    const float* Wv = (const float*)d_in[5];
    const float* bv = (const float*)d_in[6];
    const float* Wo = (const float*)d_in[7];
    const float* bo = (const float*)d_in[8];
    float* out = (float*)d_out;

    float *qp, *kp, *vp, *op;
    cudaGetSymbolAddress((void**)&qp, g_Q);
    cudaGetSymbolAddress((void**)&kp, g_K);
    cudaGetSymbolAddress((void**)&vp, g_V);
    cudaGetSymbolAddress((void**)&op, g_O);

    cudaFuncSetAttribute(attn_kernel,
                         cudaFuncAttributeMaxDynamicSharedMemorySize,
                         ATTN_SMEM_BYTES);

    dim3 gg(EMB / 128, M_TOTAL / 128);   // (8, 64)
    sgemm_bias<<<gg, 256>>>(x, Wq, bq, qp);
    sgemm_bias<<<gg, 256>>>(x, Wk, bk, kp);
    sgemm_bias<<<gg, 256>>>(x, Wv, bv, vp);

    attn_kernel<<<dim3(S_LEN / 64, BATCH * NH), 256, ATTN_SMEM_BYTES>>>(qp, kp, vp, op);

    sgemm_bias<<<gg, 256>>>(op, Wo, bo, out);
}

// round 3
// speedup vs baseline: 1.3538x; 1.3538x over previous
#include <cuda_runtime.h>
#include <cuda_bf16.h>
#include <math.h>
#include <stdint.h>

#define EMB    1024
#define S_LEN  2048
#define BATCH  4
#define NH     16
#define HD     64
#define M_TOTAL (BATCH * S_LEN)   // 8192
#define QKV_LD 3072

__device__ __forceinline__ uint32_t smem_to_u32(const void* p) {
    uint32_t a;
    asm("{ .reg .u64 t; cvta.to.shared.u64 t, %1; cvt.u32.u64 %0, t; }"
        : "=r"(a) : "l"(p));
    return a;
}
__device__ __forceinline__ void cpa16(uint32_t s, const void* g) {
    asm volatile("cp.async.cg.shared.global [%0], [%1], 16;\n" :: "r"(s), "l"(g));
}
__device__ __forceinline__ void ldm_x4(uint32_t& r0, uint32_t& r1, uint32_t& r2,
                                       uint32_t& r3, uint32_t addr) {
    asm volatile("ldmatrix.sync.aligned.m8n8.x4.shared.b16 {%0,%1,%2,%3}, [%4];"
                 : "=r"(r0), "=r"(r1), "=r"(r2), "=r"(r3) : "r"(addr));
}
__device__ __forceinline__ void mma_bf16(float& c0, float& c1, float& c2, float& c3,
                                         uint32_t a0, uint32_t a1, uint32_t a2, uint32_t a3,
                                         uint32_t b0, uint32_t b1) {
    asm volatile("mma.sync.aligned.m16n8k16.row.col.f32.bf16.bf16.f32 "
                 "{%0,%1,%2,%3}, {%4,%5,%6,%7}, {%8,%9}, {%0,%1,%2,%3};"
                 : "+f"(c0), "+f"(c1), "+f"(c2), "+f"(c3)
                 : "r"(a0), "r"(a1), "r"(a2), "r"(a3), "r"(b0), "r"(b1));
}

// ======================= scratch globals ====================================
__device__ __nv_bfloat16 g_xh[(size_t)M_TOTAL * EMB];
__device__ __nv_bfloat16 g_xl[(size_t)M_TOTAL * EMB];
__device__ __nv_bfloat16 g_WTqkv_h[(size_t)QKV_LD * EMB];
__device__ __nv_bfloat16 g_WTqkv_l[(size_t)QKV_LD * EMB];
__device__ __nv_bfloat16 g_WTo_h[(size_t)EMB * EMB];
__device__ __nv_bfloat16 g_WTo_l[(size_t)EMB * EMB];
__device__ float g_biasqkv[QKV_LD];
__device__ float g_QKV[(size_t)M_TOTAL * QKV_LD];
__device__ float g_O[(size_t)M_TOTAL * EMB];
__device__ __nv_bfloat16 g_Oh[(size_t)M_TOTAL * EMB];
__device__ __nv_bfloat16 g_Ol[(size_t)M_TOTAL * EMB];

// ======================= conversion kernels =================================
__global__ void split_f32_bf16(const float* __restrict__ in,
                               __nv_bfloat16* __restrict__ hi,
                               __nv_bfloat16* __restrict__ lo, int n4) {
    int i = blockIdx.x * blockDim.x + threadIdx.x;
    if (i >= n4) return;
    float4 v = ((const float4*)in)[i];
    __nv_bfloat16 ha = __float2bfloat16_rn(v.x);
    __nv_bfloat16 hb = __float2bfloat16_rn(v.y);
    __nv_bfloat16 hc = __float2bfloat16_rn(v.z);
    __nv_bfloat16 hd = __float2bfloat16_rn(v.w);
    __nv_bfloat16 la = __float2bfloat16_rn(v.x - __bfloat162float(ha));
    __nv_bfloat16 lb = __float2bfloat16_rn(v.y - __bfloat162float(hb));
    __nv_bfloat16 lc = __float2bfloat16_rn(v.z - __bfloat162float(hc));
    __nv_bfloat16 ld = __float2bfloat16_rn(v.w - __bfloat162float(hd));
    __nv_bfloat162* H = (__nv_bfloat162*)hi;
    __nv_bfloat162* L = (__nv_bfloat162*)lo;
    H[2 * i]     = __nv_bfloat162(ha, hb);
    H[2 * i + 1] = __nv_bfloat162(hc, hd);
    L[2 * i]     = __nv_bfloat162(la, lb);
    L[2 * i + 1] = __nv_bfloat162(lc, ld);
}

// W[k][n] (1024x1024) -> WT[n][k] split into hi/lo bf16
__global__ void wsplit_t(const float* __restrict__ W,
                         __nv_bfloat16* __restrict__ WTh,
                         __nv_bfloat16* __restrict__ WTl) {
    __shared__ float t[32][33];
    const int n0 = blockIdx.x * 32, k0 = blockIdx.y * 32;
    const int tx = threadIdx.x, ty = threadIdx.y;
    #pragma unroll
    for (int r = 0; r < 32; r += 8)
        t[ty + r][tx] = W[(size_t)(k0 + ty + r) * EMB + n0 + tx];
    __syncthreads();
    #pragma unroll
    for (int r = 0; r < 32; r += 8) {
        float v = t[tx][ty + r];
        __nv_bfloat16 h = __float2bfloat16_rn(v);
        __nv_bfloat16 l = __float2bfloat16_rn(v - __bfloat162float(h));
        WTh[(size_t)(n0 + ty + r) * EMB + k0 + tx] = h;
        WTl[(size_t)(n0 + ty + r) * EMB + k0 + tx] = l;
    }
}

__global__ void concat_bias(const float* __restrict__ bq, const float* __restrict__ bk,
                            const float* __restrict__ bv, float* __restrict__ o) {
    int i = blockIdx.x * blockDim.x + threadIdx.x;
    if (i < EMB) { o[i] = bq[i]; o[EMB + i] = bk[i]; o[2 * EMB + i] = bv[i]; }
}

// ======================= mma.sync split-bf16 GEMM ===========================
// C[M x N] = (Ah+Al)[M x 1024] @ (Bh+Bl)^T[N x 1024] + bias
// Virtual K = 3072 (3 passes: Ah*Bh, Al*Bh, Ah*Bl), chunk = 64, 3 smem stages.
// CTA tile 128x128, 8 warps (2 M x 4 N), warp tile 64x32.
#define GT_M 128
#define GT_N 128
#define KCH  64
#define NCH  48
#define STAGE_BYTES (2 * GT_M * 128)     // A 16KB + B 16KB
#define GEMM_SMEM_BYTES (3 * STAGE_BYTES)

__global__ __launch_bounds__(256, 1)
void gemm_bf16s(const __nv_bfloat16* __restrict__ Ah, const __nv_bfloat16* __restrict__ Al,
                const __nv_bfloat16* __restrict__ Bh, const __nv_bfloat16* __restrict__ Bl,
                const float* __restrict__ bias, float* __restrict__ C, int ldC) {
    extern __shared__ char smem[];
    const uint32_t sb = smem_to_u32(smem);
    const int tid  = threadIdx.x;
    const int wid  = tid >> 5;
    const int lane = tid & 31;
    const int wm = wid & 1;          // 0..1 (64 rows each)
    const int wn = wid >> 1;         // 0..3 (32 cols each)
    const int m0 = blockIdx.y * GT_M;
    const int n0 = blockIdx.x * GT_N;

    const __nv_bfloat16* Ap[3] = {Ah, Al, Ah};
    const __nv_bfloat16* Bp[3] = {Bh, Bh, Bl};

    // per-thread cp.async mapping: 4 granules of 16B each for A and for B
    const int ldrow = tid >> 1;                 // 0..127 (two granule-pairs/row? no:)
    // idx = tid + j*256 ; row = idx>>3 ; g = idx&7
    auto load_chunk = [&](int ci) {
        const int pass = ci >> 4, kc = ci & 15;
        const __nv_bfloat16* A = Ap[pass];
        const __nv_bfloat16* B = Bp[pass];
        const uint32_t ab = sb + (ci % 3) * STAGE_BYTES;
        const uint32_t bb = ab + GT_M * 128;
        #pragma unroll
        for (int j = 0; j < 4; ++j) {
            const int idx = tid + j * 256;
            const int row = idx >> 3, g = idx & 7;
            const uint32_t off = row * 128 + ((g * 16) ^ ((row & 7) << 4));
            cpa16(ab + off, A + (size_t)(m0 + row) * EMB + kc * KCH + g * 8);
        }
        #pragma unroll
        for (int j = 0; j < 4; ++j) {
            const int idx = tid + j * 256;
            const int row = idx >> 3, g = idx & 7;
            const uint32_t off = row * 128 + ((g * 16) ^ ((row & 7) << 4));
            cpa16(bb + off, B + (size_t)(n0 + row) * EMB + kc * KCH + g * 8);
        }
        asm volatile("cp.async.commit_group;\n" ::: "memory");
    };
    (void)ldrow;

    float acc[4][4][4];
    #pragma unroll
    for (int mt = 0; mt < 4; ++mt)
        #pragma unroll
        for (int nt = 0; nt < 4; ++nt)
            #pragma unroll
            for (int r = 0; r < 4; ++r) acc[mt][nt][r] = 0.0f;

    // per-lane ldmatrix address components
    const int arow_l  = wm * 64 + (lane & 15);       // + mt*16
    const int akb_l   = (lane >> 4) * 16;            // + k16*32
    const int asx     = (arow_l & 7) << 4;
    const int brow_l  = wn * 32 + (lane & 7) + ((lane >> 4) & 1) * 8;  // + nt2*16
    const int bkb_l   = ((lane >> 3) & 1) * 16;
    const int bsx     = (brow_l & 7) << 4;

    load_chunk(0);
    load_chunk(1);

    for (int i = 0; i < NCH; ++i) {
        if (i + 1 < NCH) asm volatile("cp.async.wait_group 1;\n" ::: "memory");
        else             asm volatile("cp.async.wait_group 0;\n" ::: "memory");
        __syncthreads();

        if (i + 2 < NCH) load_chunk(i + 2);

        const uint32_t ab = sb + (i % 3) * STAGE_BYTES;
        const uint32_t bb = ab + GT_M * 128;

        #pragma unroll
        for (int k16 = 0; k16 < 4; ++k16) {
            const int kb = k16 * 32;
            uint32_t a[4][4];
            #pragma unroll
            for (int mt = 0; mt < 4; ++mt) {
                const int row = arow_l + mt * 16;
                ldm_x4(a[mt][0], a[mt][1], a[mt][2], a[mt][3],
                       ab + row * 128 + ((kb + akb_l) ^ asx));
            }
            uint32_t b[4][2];
            #pragma unroll
            for (int nt2 = 0; nt2 < 2; ++nt2) {
                const int row = brow_l + nt2 * 16;
                uint32_t r0, r1, r2, r3;
                ldm_x4(r0, r1, r2, r3, bb + row * 128 + ((kb + bkb_l) ^ bsx));
                b[nt2 * 2][0] = r0; b[nt2 * 2][1] = r1;
                b[nt2 * 2 + 1][0] = r2; b[nt2 * 2 + 1][1] = r3;
            }
            #pragma unroll
            for (int mt = 0; mt < 4; ++mt)
                #pragma unroll
                for (int nt = 0; nt < 4; ++nt)
                    mma_bf16(acc[mt][nt][0], acc[mt][nt][1], acc[mt][nt][2], acc[mt][nt][3],
                             a[mt][0], a[mt][1], a[mt][2], a[mt][3],
                             b[nt][0], b[nt][1]);
        }
    }

    // epilogue: direct float2 stores + bias
    const int rbase = m0 + wm * 64 + (lane >> 2);
    const int cbase = n0 + wn * 32 + (lane & 3) * 2;
    #pragma unroll
    for (int mt = 0; mt < 4; ++mt) {
        #pragma unroll
        for (int nt = 0; nt < 4; ++nt) {
            const int c = cbase + nt * 8;
            const float b0 = bias[c], b1 = bias[c + 1];
            float2 v0, v1;
            v0.x = acc[mt][nt][0] + b0; v0.y = acc[mt][nt][1] + b1;
            v1.x = acc[mt][nt][2] + b0; v1.y = acc[mt][nt][3] + b1;
            *(float2*)&C[(size_t)(rbase + mt * 16) * ldC + c] = v0;
            *(float2*)&C[(size_t)(rbase + mt * 16 + 8) * ldC + c] = v1;
        }
    }
}

// ======================= flash attention (fp32 SIMT) ========================
#define KT_STR 65
#define ATTN_SMEM_FLOATS (64*64 + 64*KT_STR + 64*64)
#define ATTN_SMEM_BYTES  (ATTN_SMEM_FLOATS * 4)

__global__ __launch_bounds__(256, 2)
void attn_kernel(const float* __restrict__ QKV, float* __restrict__ O) {
    extern __shared__ float sm[];
    float* Qs = sm;
    float* KT = sm + 64 * 64;
    float* Ps = KT;
    float* Vs = sm + 64 * 64 + 64 * KT_STR;

    const int tid = threadIdx.x;
    const int tx  = tid & 15;
    const int ty  = tid >> 4;
    const int ty4 = ty * 4;
    const int tx4 = tx * 4;

    const int bh = blockIdx.y;
    const int b  = bh >> 4;
    const int h  = bh & 15;
    const int qbase = blockIdx.x * 64;

    const float* Qg = QKV + (size_t)b * S_LEN * QKV_LD + h * HD;
    const float* Kg = Qg + EMB;
    const float* Vg = Qg + 2 * EMB;

    const int lr  = tid >> 4;
    const int lc4 = (tid & 15) << 2;

    #pragma unroll
    for (int u = 0; u < 4; ++u) {
        const int r = lr + u * 16;
        float4 v = *(const float4*)(Qg + (size_t)(qbase + r) * QKV_LD + lc4);
        *(float4*)&Qs[r * 64 + lc4] = v;
    }

    float m_i[4], l_i[4], acc[4][4];
    #pragma unroll
    for (int i = 0; i < 4; ++i) {
        m_i[i] = -INFINITY; l_i[i] = 0.0f;
        #pragma unroll
        for (int j = 0; j < 4; ++j) acc[i][j] = 0.0f;
    }

    float4 kreg[4];
    #pragma unroll
    for (int u = 0; u < 4; ++u)
        kreg[u] = *(const float4*)(Kg + (size_t)(lr + u * 16) * QKV_LD + lc4);

    __syncthreads();

    const int NT = S_LEN / 64;
    for (int t = 0; t < NT; ++t) {
        #pragma unroll
        for (int u = 0; u < 4; ++u) {
            const int kv = lr + u * 16;
            KT[(lc4 + 0) * KT_STR + kv] = kreg[u].x;
            KT[(lc4 + 1) * KT_STR + kv] = kreg[u].y;
            KT[(lc4 + 2) * KT_STR + kv] = kreg[u].z;
            KT[(lc4 + 3) * KT_STR + kv] = kreg[u].w;
        }
        __syncthreads();

        float4 vreg[4];
        #pragma unroll
        for (int u = 0; u < 4; ++u)
            vreg[u] = *(const float4*)(Vg + (size_t)(t * 64 + lr + u * 16) * QKV_LD + lc4);

        float s[4][4];
        #pragma unroll
        for (int i = 0; i < 4; ++i)
            #pragma unroll
            for (int j = 0; j < 4; ++j) s[i][j] = 0.0f;

        for (int k = 0; k < 64; k += 4) {
            float aq[4][4];
            #pragma unroll
            for (int i = 0; i < 4; ++i)
                *(float4*)&aq[i][0] = *(const float4*)&Qs[(ty4 + i) * 64 + k];
            #pragma unroll
            for (int kk = 0; kk < 4; ++kk) {
                float bb[4];
                #pragma unroll
                for (int j = 0; j < 4; ++j)
                    bb[j] = KT[(k + kk) * KT_STR + tx4 + j];
                #pragma unroll
                for (int i = 0; i < 4; ++i)
                    #pragma unroll
                    for (int j = 0; j < 4; ++j)
                        s[i][j] = fmaf(aq[i][kk], bb[j], s[i][j]);
            }
        }
        #pragma unroll
        for (int i = 0; i < 4; ++i)
            #pragma unroll
            for (int j = 0; j < 4; ++j) s[i][j] *= 0.125f;

        float mt[4];
        #pragma unroll
        for (int i = 0; i < 4; ++i) {
            mt[i] = fmaxf(fmaxf(s[i][0], s[i][1]), fmaxf(s[i][2], s[i][3]));
            #pragma unroll
            for (int off = 8; off > 0; off >>= 1)
                mt[i] = fmaxf(mt[i], __shfl_xor_sync(0xffffffffu, mt[i], off));
        }

        float rs[4], corr[4];
        #pragma unroll
        for (int i = 0; i < 4; ++i) {
            const float mnew = fmaxf(m_i[i], mt[i]);
            corr[i] = __expf(m_i[i] - mnew);
            m_i[i] = mnew;
            float r = 0.0f;
            #pragma unroll
            for (int j = 0; j < 4; ++j) {
                s[i][j] = __expf(s[i][j] - mnew);
                r += s[i][j];
            }
            rs[i] = r;
        }
        #pragma unroll
        for (int i = 0; i < 4; ++i) {
            #pragma unroll
            for (int off = 8; off > 0; off >>= 1)
                rs[i] += __shfl_xor_sync(0xffffffffu, rs[i], off);
            l_i[i] = l_i[i] * corr[i] + rs[i];
            #pragma unroll
            for (int j = 0; j < 4; ++j) acc[i][j] *= corr[i];
        }

        __syncthreads();

        #pragma unroll
        for (int i = 0; i < 4; ++i) {
            float4 p4;
            p4.x = s[i][0]; p4.y = s[i][1]; p4.z = s[i][2]; p4.w = s[i][3];
            *(float4*)&Ps[(ty4 + i) * 64 + tx4] = p4;
        }
        #pragma unroll
        for (int u = 0; u < 4; ++u)
            *(float4*)&Vs[(lr + u * 16) * 64 + lc4] = vreg[u];

        if (t + 1 < NT) {
            #pragma unroll
            for (int u = 0; u < 4; ++u)
                kreg[u] = *(const float4*)(Kg + (size_t)((t + 1) * 64 + lr + u * 16) * QKV_LD + lc4);
        }
        __syncthreads();

        for (int kv = 0; kv < 64; kv += 4) {
            float pq[4][4];
            #pragma unroll
            for (int i = 0; i < 4; ++i)
                *(float4*)&pq[i][0] = *(const float4*)&Ps[(ty4 + i) * 64 + kv];
            #pragma unroll
            for (int u = 0; u < 4; ++u) {
                float4 vv = *(const float4*)&Vs[(kv + u) * 64 + tx4];
                #pragma unroll
                for (int i = 0; i < 4; ++i) {
                    acc[i][0] = fmaf(pq[i][u], vv.x, acc[i][0]);
                    acc[i][1] = fmaf(pq[i][u], vv.y, acc[i][1]);
                    acc[i][2] = fmaf(pq[i][u], vv.z, acc[i][2]);
                    acc[i][3] = fmaf(pq[i][u], vv.w, acc[i][3]);
                }
            }
        }
        __syncthreads();
    }

    #pragma unroll
    for (int i = 0; i < 4; ++i) {
        const float inv = 1.0f / l_i[i];
        const int row = qbase + ty4 + i;
        float4 o;
        o.x = acc[i][0] * inv;
        o.y = acc[i][1] * inv;
        o.z = acc[i][2] * inv;
        o.w = acc[i][3] * inv;
        *(float4*)&g_O[(size_t)(b * S_LEN + row) * EMB + h * HD + tx4] = o;
    }
}

// ======================= launch =============================================
extern "C" void kernel_launch(void* const* d_in, const int* in_sizes, int n_in,
                              void* d_out, int out_size) {
    const float* x  = (const float*)d_in[0];
    const float* Wq = (const float*)d_in[1];
    const float* bq = (const float*)d_in[2];
    const float* Wk = (const float*)d_in[3];
    const float* bk = (const float*)d_in[4];
    const float* Wv = (const float*)d_in[5];
    const float* bv = (const float*)d_in[6];
    const float* Wo = (const float*)d_in[7];
    const float* bo = (const float*)d_in[8];
    float* out = (float*)d_out;

    __nv_bfloat16 *xh, *xl, *wqh, *wql, *woh, *wol, *oh, *ol;
    float *qkv, *o, *bqkv;
    cudaGetSymbolAddress((void**)&xh, g_xh);
    cudaGetSymbolAddress((void**)&xl, g_xl);
    cudaGetSymbolAddress((void**)&wqh, g_WTqkv_h);
    cudaGetSymbolAddress((void**)&wql, g_WTqkv_l);
    cudaGetSymbolAddress((void**)&woh, g_WTo_h);
    cudaGetSymbolAddress((void**)&wol, g_WTo_l);
    cudaGetSymbolAddress((void**)&oh, g_Oh);
    cudaGetSymbolAddress((void**)&ol, g_Ol);
    cudaGetSymbolAddress((void**)&qkv, g_QKV);
    cudaGetSymbolAddress((void**)&o, g_O);
    cudaGetSymbolAddress((void**)&bqkv, g_biasqkv);

    cudaFuncSetAttribute(gemm_bf16s, cudaFuncAttributeMaxDynamicSharedMemorySize,
                         GEMM_SMEM_BYTES);
    cudaFuncSetAttribute(attn_kernel, cudaFuncAttributeMaxDynamicSharedMemorySize,
                         ATTN_SMEM_BYTES);

    const int n4 = M_TOTAL * EMB / 4;
    split_f32_bf16<<<(n4 + 255) / 256, 256>>>(x, xh, xl, n4);
    wsplit_t<<<dim3(32, 32), dim3(32, 8)>>>(Wq, wqh, wql);
    wsplit_t<<<dim3(32, 32), dim3(32, 8)>>>(Wk, wqh + (size_t)EMB * EMB, wql + (size_t)EMB * EMB);
    wsplit_t<<<dim3(32, 32), dim3(32, 8)>>>(Wv, wqh + (size_t)2 * EMB * EMB, wql + (size_t)2 * EMB * EMB);
    wsplit_t<<<dim3(32, 32), dim3(32, 8)>>>(Wo, woh, wol);
    concat_bias<<<4, 256>>>(bq, bk, bv, bqkv);

    gemm_bf16s<<<dim3(QKV_LD / GT_N, M_TOTAL / GT_M), 256, GEMM_SMEM_BYTES>>>(
        xh, xl, wqh, wql, bqkv, qkv, QKV_LD);

    attn_kernel<<<dim3(S_LEN / 64, BATCH * NH), 256, ATTN_SMEM_BYTES>>>(qkv, o);

    split_f32_bf16<<<(n4 + 255) / 256, 256>>>(o, oh, ol, n4);

    gemm_bf16s<<<dim3(EMB / GT_N, M_TOTAL / GT_M), 256, GEMM_SMEM_BYTES>>>(
        oh, ol, woh, wol, bo, out, EMB);
}

// round 4
// speedup vs baseline: 3.0542x; 2.2561x over previous
#include <cuda_runtime.h>
#include <cuda_bf16.h>
#include <math.h>
#include <stdint.h>

#define EMB    1024
#define S_LEN  2048
#define BATCH  4
#define NH     16
#define HD     64
#define M_TOTAL (BATCH * S_LEN)   // 8192
#define QKV_LD 3072

__device__ __forceinline__ uint32_t smem_to_u32(const void* p) {
    uint32_t a;
    asm("{ .reg .u64 t; cvta.to.shared.u64 t, %1; cvt.u32.u64 %0, t; }"
        : "=r"(a) : "l"(p));
    return a;
}
__device__ __forceinline__ void cpa16(uint32_t s, const void* g) {
    asm volatile("cp.async.cg.shared.global [%0], [%1], 16;\n" :: "r"(s), "l"(g));
}
__device__ __forceinline__ void ldm_x4(uint32_t& r0, uint32_t& r1, uint32_t& r2,
                                       uint32_t& r3, uint32_t addr) {
    asm volatile("ldmatrix.sync.aligned.m8n8.x4.shared.b16 {%0,%1,%2,%3}, [%4];"
                 : "=r"(r0), "=r"(r1), "=r"(r2), "=r"(r3) : "r"(addr));
}
__device__ __forceinline__ void ldm_x4t(uint32_t& r0, uint32_t& r1, uint32_t& r2,
                                        uint32_t& r3, uint32_t addr) {
    asm volatile("ldmatrix.sync.aligned.m8n8.x4.trans.shared.b16 {%0,%1,%2,%3}, [%4];"
                 : "=r"(r0), "=r"(r1), "=r"(r2), "=r"(r3) : "r"(addr));
}
__device__ __forceinline__ void mma_bf16(float& c0, float& c1, float& c2, float& c3,
                                         uint32_t a0, uint32_t a1, uint32_t a2, uint32_t a3,
                                         uint32_t b0, uint32_t b1) {
    asm volatile("mma.sync.aligned.m16n8k16.row.col.f32.bf16.bf16.f32 "
                 "{%0,%1,%2,%3}, {%4,%5,%6,%7}, {%8,%9}, {%0,%1,%2,%3};"
                 : "+f"(c0), "+f"(c1), "+f"(c2), "+f"(c3)
                 : "r"(a0), "r"(a1), "r"(a2), "r"(a3), "r"(b0), "r"(b1));
}
__device__ __forceinline__ float ex2f(float x) {
    float r; asm("ex2.approx.f32 %0, %1;" : "=f"(r) : "f"(x)); return r;
}
// split v into hi (truncated bf16) + lo; return packed hi pair + lo floats
__device__ __forceinline__ void split2_pack(float v0, float v1, uint32_t& hpack,
                                            float& l0, float& l1) {
    uint32_t u0 = __float_as_uint(v0), u1 = __float_as_uint(v1);
    hpack = (u1 & 0xFFFF0000u) | (u0 >> 16);
    l0 = v0 - __uint_as_float(u0 & 0xFFFF0000u);
    l1 = v1 - __uint_as_float(u1 & 0xFFFF0000u);
}

// ======================= scratch globals ====================================
__device__ __nv_bfloat16 g_xh[(size_t)M_TOTAL * EMB];
__device__ __nv_bfloat16 g_xl[(size_t)M_TOTAL * EMB];
__device__ __nv_bfloat16 g_WTqkv_h[(size_t)QKV_LD * EMB];
__device__ __nv_bfloat16 g_WTqkv_l[(size_t)QKV_LD * EMB];
__device__ __nv_bfloat16 g_WTo_h[(size_t)EMB * EMB];
__device__ __nv_bfloat16 g_WTo_l[(size_t)EMB * EMB];
__device__ float g_biasqkv[QKV_LD];
__device__ __nv_bfloat16 g_QKVh[(size_t)M_TOTAL * QKV_LD];
__device__ __nv_bfloat16 g_QKVl[(size_t)M_TOTAL * QKV_LD];
__device__ __nv_bfloat16 g_Oh[(size_t)M_TOTAL * EMB];
__device__ __nv_bfloat16 g_Ol[(size_t)M_TOTAL * EMB];

// ======================= conversion kernels =================================
__global__ void split_f32_bf16(const float* __restrict__ in,
                               __nv_bfloat16* __restrict__ hi,
                               __nv_bfloat16* __restrict__ lo, int n4) {
    int i = blockIdx.x * blockDim.x + threadIdx.x;
    if (i >= n4) return;
    float4 v = ((const float4*)in)[i];
    __nv_bfloat16 ha = __float2bfloat16_rn(v.x);
    __nv_bfloat16 hb = __float2bfloat16_rn(v.y);
    __nv_bfloat16 hc = __float2bfloat16_rn(v.z);
    __nv_bfloat16 hd = __float2bfloat16_rn(v.w);
    __nv_bfloat16 la = __float2bfloat16_rn(v.x - __bfloat162float(ha));
    __nv_bfloat16 lb = __float2bfloat16_rn(v.y - __bfloat162float(hb));
    __nv_bfloat16 lc = __float2bfloat16_rn(v.z - __bfloat162float(hc));
    __nv_bfloat16 ld = __float2bfloat16_rn(v.w - __bfloat162float(hd));
    __nv_bfloat162* H = (__nv_bfloat162*)hi;
    __nv_bfloat162* L = (__nv_bfloat162*)lo;
    H[2 * i]     = __nv_bfloat162(ha, hb);
    H[2 * i + 1] = __nv_bfloat162(hc, hd);
    L[2 * i]     = __nv_bfloat162(la, lb);
    L[2 * i + 1] = __nv_bfloat162(lc, ld);
}

__global__ void wsplit_t(const float* __restrict__ W,
                         __nv_bfloat16* __restrict__ WTh,
                         __nv_bfloat16* __restrict__ WTl) {
    __shared__ float t[32][33];
    const int n0 = blockIdx.x * 32, k0 = blockIdx.y * 32;
    const int tx = threadIdx.x, ty = threadIdx.y;
    #pragma unroll
    for (int r = 0; r < 32; r += 8)
        t[ty + r][tx] = W[(size_t)(k0 + ty + r) * EMB + n0 + tx];
    __syncthreads();
    #pragma unroll
    for (int r = 0; r < 32; r += 8) {
        float v = t[tx][ty + r];
        __nv_bfloat16 h = __float2bfloat16_rn(v);
        __nv_bfloat16 l = __float2bfloat16_rn(v - __bfloat162float(h));
        WTh[(size_t)(n0 + ty + r) * EMB + k0 + tx] = h;
        WTl[(size_t)(n0 + ty + r) * EMB + k0 + tx] = l;
    }
}

__global__ void concat_bias(const float* __restrict__ bq, const float* __restrict__ bk,
                            const float* __restrict__ bv, float* __restrict__ o) {
    int i = blockIdx.x * blockDim.x + threadIdx.x;
    if (i < EMB) { o[i] = bq[i]; o[EMB + i] = bk[i]; o[2 * EMB + i] = bv[i]; }
}

// ======================= mma.sync split-bf16 GEMM ===========================
#define GT_M 128
#define GT_N 128
#define KCH  64
#define NCH  48
#define STAGE_BYTES (2 * GT_M * 128)
#define GEMM_SMEM_BYTES (3 * STAGE_BYTES)

__global__ __launch_bounds__(256, 1)
void gemm_bf16s(const __nv_bfloat16* __restrict__ Ah, const __nv_bfloat16* __restrict__ Al,
                const __nv_bfloat16* __restrict__ Bh, const __nv_bfloat16* __restrict__ Bl,
                const float* __restrict__ bias,
                float* __restrict__ Cf,                 // fp32 out (or null)
                __nv_bfloat16* __restrict__ Ch,         // split bf16 out
                __nv_bfloat16* __restrict__ Cl,
                int ldC) {
    extern __shared__ char smem[];
    const uint32_t sb = smem_to_u32(smem);
    const int tid  = threadIdx.x;
    const int wid  = tid >> 5;
    const int lane = tid & 31;
    const int wm = wid & 1;
    const int wn = wid >> 1;
    const int m0 = blockIdx.y * GT_M;
    const int n0 = blockIdx.x * GT_N;

    const __nv_bfloat16* Ap[3] = {Ah, Al, Ah};
    const __nv_bfloat16* Bp[3] = {Bh, Bh, Bl};

    auto load_chunk = [&](int ci) {
        const int pass = ci >> 4, kc = ci & 15;
        const __nv_bfloat16* A = Ap[pass];
        const __nv_bfloat16* B = Bp[pass];
        const uint32_t ab = sb + (ci % 3) * STAGE_BYTES;
        const uint32_t bb = ab + GT_M * 128;
        #pragma unroll
        for (int j = 0; j < 4; ++j) {
            const int idx = tid + j * 256;
            const int row = idx >> 3, g = idx & 7;
            const uint32_t off = row * 128 + ((g * 16) ^ ((row & 7) << 4));
            cpa16(ab + off, A + (size_t)(m0 + row) * EMB + kc * KCH + g * 8);
        }
        #pragma unroll
        for (int j = 0; j < 4; ++j) {
            const int idx = tid + j * 256;
            const int row = idx >> 3, g = idx & 7;
            const uint32_t off = row * 128 + ((g * 16) ^ ((row & 7) << 4));
            cpa16(bb + off, B + (size_t)(n0 + row) * EMB + kc * KCH + g * 8);
        }
        asm volatile("cp.async.commit_group;\n" ::: "memory");
    };

    float acc[4][4][4];
    #pragma unroll
    for (int mt = 0; mt < 4; ++mt)
        #pragma unroll
        for (int nt = 0; nt < 4; ++nt)
            #pragma unroll
            for (int r = 0; r < 4; ++r) acc[mt][nt][r] = 0.0f;

    const int arow_l  = wm * 64 + (lane & 15);
    const int akb_l   = (lane >> 4) * 16;
    const int asx     = (arow_l & 7) << 4;
    const int brow_l  = wn * 32 + (lane & 7) + ((lane >> 4) & 1) * 8;
    const int bkb_l   = ((lane >> 3) & 1) * 16;
    const int bsx     = (brow_l & 7) << 4;

    load_chunk(0);
    load_chunk(1);

    for (int i = 0; i < NCH; ++i) {
        if (i + 1 < NCH) asm volatile("cp.async.wait_group 1;\n" ::: "memory");
        else             asm volatile("cp.async.wait_group 0;\n" ::: "memory");
        __syncthreads();

        if (i + 2 < NCH) load_chunk(i + 2);

        const uint32_t ab = sb + (i % 3) * STAGE_BYTES;
        const uint32_t bb = ab + GT_M * 128;

        #pragma unroll
        for (int k16 = 0; k16 < 4; ++k16) {
            const int kb = k16 * 32;
            uint32_t a[4][4];
            #pragma unroll
            for (int mt = 0; mt < 4; ++mt) {
                const int row = arow_l + mt * 16;
                ldm_x4(a[mt][0], a[mt][1], a[mt][2], a[mt][3],
                       ab + row * 128 + ((kb + akb_l) ^ asx));
            }
            uint32_t b[4][2];
            #pragma unroll
            for (int nt2 = 0; nt2 < 2; ++nt2) {
                const int row = brow_l + nt2 * 16;
                uint32_t r0, r1, r2, r3;
                ldm_x4(r0, r1, r2, r3, bb + row * 128 + ((kb + bkb_l) ^ bsx));
                b[nt2 * 2][0] = r0; b[nt2 * 2][1] = r1;
                b[nt2 * 2 + 1][0] = r2; b[nt2 * 2 + 1][1] = r3;
            }
            #pragma unroll
            for (int mt = 0; mt < 4; ++mt)
                #pragma unroll
                for (int nt = 0; nt < 4; ++nt)
                    mma_bf16(acc[mt][nt][0], acc[mt][nt][1], acc[mt][nt][2], acc[mt][nt][3],
                             a[mt][0], a[mt][1], a[mt][2], a[mt][3],
                             b[nt][0], b[nt][1]);
        }
    }

    const int rbase = m0 + wm * 64 + (lane >> 2);
    const int cbase = n0 + wn * 32 + (lane & 3) * 2;
    if (Cf) {
        #pragma unroll
        for (int mt = 0; mt < 4; ++mt) {
            #pragma unroll
            for (int nt = 0; nt < 4; ++nt) {
                const int c = cbase + nt * 8;
                const float b0 = bias[c], b1 = bias[c + 1];
                float2 v0, v1;
                v0.x = acc[mt][nt][0] + b0; v0.y = acc[mt][nt][1] + b1;
                v1.x = acc[mt][nt][2] + b0; v1.y = acc[mt][nt][3] + b1;
                *(float2*)&Cf[(size_t)(rbase + mt * 16) * ldC + c] = v0;
                *(float2*)&Cf[(size_t)(rbase + mt * 16 + 8) * ldC + c] = v1;
            }
        }
    } else {
        #pragma unroll
        for (int mt = 0; mt < 4; ++mt) {
            #pragma unroll
            for (int nt = 0; nt < 4; ++nt) {
                const int c = cbase + nt * 8;
                const float b0 = bias[c], b1 = bias[c + 1];
                float v0 = acc[mt][nt][0] + b0, v1 = acc[mt][nt][1] + b1;
                float v2 = acc[mt][nt][2] + b0, v3 = acc[mt][nt][3] + b1;
                uint32_t h01, h23; float l0, l1, l2, l3;
                split2_pack(v0, v1, h01, l0, l1);
                split2_pack(v2, v3, h23, l2, l3);
                __nv_bfloat162 lp01 = __floats2bfloat162_rn(l0, l1);
                __nv_bfloat162 lp23 = __floats2bfloat162_rn(l2, l3);
                const size_t o0 = (size_t)(rbase + mt * 16) * ldC + c;
                const size_t o1 = (size_t)(rbase + mt * 16 + 8) * ldC + c;
                *(uint32_t*)(Ch + o0) = h01;
                *(uint32_t*)(Cl + o0) = *(uint32_t*)&lp01;
                *(uint32_t*)(Ch + o1) = h23;
                *(uint32_t*)(Cl + o1) = *(uint32_t*)&lp23;
            }
        }
    }
}

// ======================= tensor-core flash attention ========================
// CTA: 128 q-rows x full flash loop over 32 kv-tiles of 64.
// 8 warps, each owns 16 q-rows (full row -> quad-shuffle reductions only).
// smem: Qh 16K | Ql 16K | 2 stages x (Kh,Kl,Vh,Vl: 8K each) = 96KB total.
#define ATT_SMEM 98304

__global__ __launch_bounds__(256)
void attn_mma(const __nv_bfloat16* __restrict__ QKVh,
              const __nv_bfloat16* __restrict__ QKVl,
              __nv_bfloat16* __restrict__ Oh,
              __nv_bfloat16* __restrict__ Ol) {
    extern __shared__ char smem[];
    const uint32_t sb  = smem_to_u32(smem);
    const uint32_t sQh = sb;
    const uint32_t sQl = sb + 16384;
    const uint32_t sKV = sb + 32768;

    const int tid = threadIdx.x, wid = tid >> 5, lane = tid & 31;
    const int bh = blockIdx.y;
    const int b = bh >> 4, h = bh & 15;
    const int qbase = blockIdx.x * 128;
    const size_t rowbase = (size_t)b * S_LEN;

    const __nv_bfloat16* qh_g = QKVh + rowbase * QKV_LD + h * HD;
    const __nv_bfloat16* ql_g = QKVl + rowbase * QKV_LD + h * HD;
    const __nv_bfloat16* kh_g = qh_g + EMB;
    const __nv_bfloat16* kl_g = ql_g + EMB;
    const __nv_bfloat16* vh_g = qh_g + 2 * EMB;
    const __nv_bfloat16* vl_g = ql_g + 2 * EMB;

    auto ldKV = [&](int t) {
        const uint32_t base = sKV + (t & 1) * 32768;
        #pragma unroll
        for (int j = 0; j < 2; ++j) {
            const int idx = tid + j * 256;
            const int row = idx >> 3, g = idx & 7;
            const uint32_t off = row * 128 + ((g * 16) ^ ((row & 7) << 4));
            const size_t gofs = (size_t)(t * 64 + row) * QKV_LD + g * 8;
            cpa16(base + off,         kh_g + gofs);
            cpa16(base + 8192 + off,  kl_g + gofs);
            cpa16(base + 16384 + off, vh_g + gofs);
            cpa16(base + 24576 + off, vl_g + gofs);
        }
        asm volatile("cp.async.commit_group;\n" ::: "memory");
    };

    // Q tile load (group 0, committed with KV0)
    #pragma unroll
    for (int j = 0; j < 4; ++j) {
        const int idx = tid + j * 256;
        const int row = idx >> 3, g = idx & 7;
        const uint32_t off = row * 128 + ((g * 16) ^ ((row & 7) << 4));
        const size_t gofs = (size_t)(qbase + row) * QKV_LD + g * 8;
        cpa16(sQh + off, qh_g + gofs);
        cpa16(sQl + off, ql_g + gofs);
    }
    ldKV(0);
    ldKV(1);

    // fragment address components
    const int wr    = wid * 16;
    const int q_row = wr + (lane & 7) + ((lane >> 3) & 1) * 8;
    const int q_sx  = (q_row & 7) << 4;
    const int q_cb  = ((lane >> 4) & 1) * 16;           // bytes (+8 cols)
    const int k_rl  = (lane & 7) + ((lane >> 4) & 1) * 8;
    const int k_cb  = ((lane >> 3) & 1) * 16;
    const int v_rl  = (lane & 7) + ((lane >> 3) & 1) * 8;
    const int v_cb  = ((lane >> 4) & 1) * 16;

    float m0v = -INFINITY, m1v = -INFINITY, l0s = 0.0f, l1s = 0.0f;
    float acc[8][4];
    #pragma unroll
    for (int e = 0; e < 8; ++e)
        #pragma unroll
        for (int r = 0; r < 4; ++r) acc[e][r] = 0.0f;

    const float cs = 0.125f * 1.4426950408889634f;   // scale * log2(e)
    const int NT = S_LEN / 64;

    for (int t = 0; t < NT; ++t) {
        if (t + 1 < NT) asm volatile("cp.async.wait_group 1;\n" ::: "memory");
        else            asm volatile("cp.async.wait_group 0;\n" ::: "memory");
        __syncthreads();

        const uint32_t kb  = sKV + (t & 1) * 32768;
        const uint32_t klb = kb + 8192;
        const uint32_t vhb = kb + 16384;
        const uint32_t vlb = kb + 24576;

        // ---- S = Q K^T (3-pass split), fp32 accum in C-frag layout
        float s[8][4];
        #pragma unroll
        for (int e = 0; e < 8; ++e)
            #pragma unroll
            for (int r = 0; r < 4; ++r) s[e][r] = 0.0f;

        #pragma unroll
        for (int kd = 0; kd < 4; ++kd) {
            const uint32_t qoff = q_row * 128 + ((kd * 32 + q_cb) ^ q_sx);
            uint32_t qh[4], ql[4];
            ldm_x4(qh[0], qh[1], qh[2], qh[3], sQh + qoff);
            ldm_x4(ql[0], ql[1], ql[2], ql[3], sQl + qoff);
            #pragma unroll
            for (int e = 0; e < 4; ++e) {
                const int krow = e * 16 + k_rl;
                const uint32_t koff = krow * 128 + ((kd * 32 + k_cb) ^ ((krow & 7) << 4));
                uint32_t h0, h1, h2, h3, g0, g1, g2, g3;
                ldm_x4(h0, h1, h2, h3, kb + koff);
                ldm_x4(g0, g1, g2, g3, klb + koff);
                mma_bf16(s[2*e][0], s[2*e][1], s[2*e][2], s[2*e][3],
                         qh[0], qh[1], qh[2], qh[3], h0, h1);
                mma_bf16(s[2*e][0], s[2*e][1], s[2*e][2], s[2*e][3],
                         ql[0], ql[1], ql[2], ql[3], h0, h1);
                mma_bf16(s[2*e][0], s[2*e][1], s[2*e][2], s[2*e][3],
                         qh[0], qh[1], qh[2], qh[3], g0, g1);
                mma_bf16(s[2*e+1][0], s[2*e+1][1], s[2*e+1][2], s[2*e+1][3],
                         qh[0], qh[1], qh[2], qh[3], h2, h3);
                mma_bf16(s[2*e+1][0], s[2*e+1][1], s[2*e+1][2], s[2*e+1][3],
                         ql[0], ql[1], ql[2], ql[3], h2, h3);
                mma_bf16(s[2*e+1][0], s[2*e+1][1], s[2*e+1][2], s[2*e+1][3],
                         qh[0], qh[1], qh[2], qh[3], g2, g3);
            }
        }

        // ---- online softmax (base-2 domain); rows r (c0,c1) and r+8 (c2,c3)
        float r0m = -INFINITY, r1m = -INFINITY;
        #pragma unroll
        for (int e = 0; e < 8; ++e) {
            r0m = fmaxf(r0m, fmaxf(s[e][0], s[e][1]));
            r1m = fmaxf(r1m, fmaxf(s[e][2], s[e][3]));
        }
        r0m = fmaxf(r0m, __shfl_xor_sync(0xffffffffu, r0m, 1));
        r0m = fmaxf(r0m, __shfl_xor_sync(0xffffffffu, r0m, 2));
        r1m = fmaxf(r1m, __shfl_xor_sync(0xffffffffu, r1m, 1));
        r1m = fmaxf(r1m, __shfl_xor_sync(0xffffffffu, r1m, 2));

        const float mn0 = fmaxf(m0v, r0m * cs);
        const float mn1 = fmaxf(m1v, r1m * cs);
        const float cor0 = ex2f(m0v - mn0);
        const float cor1 = ex2f(m1v - mn1);
        m0v = mn0; m1v = mn1;

        float rs0 = 0.0f, rs1 = 0.0f;
        #pragma unroll
        for (int e = 0; e < 8; ++e) {
            s[e][0] = ex2f(fmaf(s[e][0], cs, -mn0)); rs0 += s[e][0];
            s[e][1] = ex2f(fmaf(s[e][1], cs, -mn0)); rs0 += s[e][1];
            s[e][2] = ex2f(fmaf(s[e][2], cs, -mn1)); rs1 += s[e][2];
            s[e][3] = ex2f(fmaf(s[e][3], cs, -mn1)); rs1 += s[e][3];
        }
        rs0 += __shfl_xor_sync(0xffffffffu, rs0, 1);
        rs0 += __shfl_xor_sync(0xffffffffu, rs0, 2);
        rs1 += __shfl_xor_sync(0xffffffffu, rs1, 1);
        rs1 += __shfl_xor_sync(0xffffffffu, rs1, 2);
        l0s = l0s * cor0 + rs0;
        l1s = l1s * cor1 + rs1;
        #pragma unroll
        for (int e = 0; e < 8; ++e) {
            acc[e][0] *= cor0; acc[e][1] *= cor0;
            acc[e][2] *= cor1; acc[e][3] *= cor1;
        }

        // ---- O += P V (3-pass split); P lives in registers
        #pragma unroll
        for (int j = 0; j < 4; ++j) {
            uint32_t aph[4], apl[4];
            {
                float la, lb;
                split2_pack(s[2*j][0],   s[2*j][1],   aph[0], la, lb);
                __nv_bfloat162 p = __floats2bfloat162_rn(la, lb);
                apl[0] = *(uint32_t*)&p;
                split2_pack(s[2*j][2],   s[2*j][3],   aph[1], la, lb);
                p = __floats2bfloat162_rn(la, lb); apl[1] = *(uint32_t*)&p;
                split2_pack(s[2*j+1][0], s[2*j+1][1], aph[2], la, lb);
                p = __floats2bfloat162_rn(la, lb); apl[2] = *(uint32_t*)&p;
                split2_pack(s[2*j+1][2], s[2*j+1][3], aph[3], la, lb);
                p = __floats2bfloat162_rn(la, lb); apl[3] = *(uint32_t*)&p;
            }
            #pragma unroll
            for (int e = 0; e < 4; ++e) {
                const int vrow = j * 16 + v_rl;
                const uint32_t voff = vrow * 128 + ((e * 32 + v_cb) ^ ((vrow & 7) << 4));
                uint32_t h0, h1, h2, h3, g0, g1, g2, g3;
                ldm_x4t(h0, h1, h2, h3, vhb + voff);
                ldm_x4t(g0, g1, g2, g3, vlb + voff);
                mma_bf16(acc[2*e][0], acc[2*e][1], acc[2*e][2], acc[2*e][3],
                         aph[0], aph[1], aph[2], aph[3], h0, h1);
                mma_bf16(acc[2*e][0], acc[2*e][1], acc[2*e][2], acc[2*e][3],
                         apl[0], apl[1], apl[2], apl[3], h0, h1);
                mma_bf16(acc[2*e][0], acc[2*e][1], acc[2*e][2], acc[2*e][3],
                         aph[0], aph[1], aph[2], aph[3], g0, g1);
                mma_bf16(acc[2*e+1][0], acc[2*e+1][1], acc[2*e+1][2], acc[2*e+1][3],
                         aph[0], aph[1], aph[2], aph[3], h2, h3);
                mma_bf16(acc[2*e+1][0], acc[2*e+1][1], acc[2*e+1][2], acc[2*e+1][3],
                         apl[0], apl[1], apl[2], apl[3], h2, h3);
                mma_bf16(acc[2*e+1][0], acc[2*e+1][1], acc[2*e+1][2], acc[2*e+1][3],
                         aph[0], aph[1], aph[2], aph[3], g2, g3);
            }
        }

        __syncthreads();
        if (t + 2 < NT) ldKV(t + 2);
    }

    // ---- epilogue: normalize, split, store bf16 hi/lo
    const float inv0 = 1.0f / l0s;
    const float inv1 = 1.0f / l1s;
    const size_t row0 = rowbase + qbase + wr + (lane >> 2);
    const size_t row1 = row0 + 8;
    const int cb = h * HD + 2 * (lane & 3);
    #pragma unroll
    for (int e = 0; e < 8; ++e) {
        const int c = cb + e * 8;
        float v0 = acc[e][0] * inv0, v1 = acc[e][1] * inv0;
        float v2 = acc[e][2] * inv1, v3 = acc[e][3] * inv1;
        uint32_t h01, h23; float l0, l1, l2, l3;
        split2_pack(v0, v1, h01, l0, l1);
        split2_pack(v2, v3, h23, l2, l3);
        __nv_bfloat162 lp01 = __floats2bfloat162_rn(l0, l1);
        __nv_bfloat162 lp23 = __floats2bfloat162_rn(l2, l3);
        *(uint32_t*)(Oh + row0 * EMB + c) = h01;
        *(uint32_t*)(Ol + row0 * EMB + c) = *(uint32_t*)&lp01;
        *(uint32_t*)(Oh + row1 * EMB + c) = h23;
        *(uint32_t*)(Ol + row1 * EMB + c) = *(uint32_t*)&lp23;
    }
}

// ======================= launch =============================================
extern "C" void kernel_launch(void* const* d_in, const int* in_sizes, int n_in,
                              void* d_out, int out_size) {
    const float* x  = (const float*)d_in[0];
    const float* Wq = (const float*)d_in[1];
    const float* bq = (const float*)d_in[2];
    const float* Wk = (const float*)d_in[3];
    const float* bk = (const float*)d_in[4];
    const float* Wv = (const float*)d_in[5];
    const float* bv = (const float*)d_in[6];
    const float* Wo = (const float*)d_in[7];
    const float* bo = (const float*)d_in[8];
    float* out = (float*)d_out;

    __nv_bfloat16 *xh, *xl, *wqh, *wql, *woh, *wol, *oh, *ol, *qkvh, *qkvl;
    float *bqkv;
    cudaGetSymbolAddress((void**)&xh, g_xh);
    cudaGetSymbolAddress((void**)&xl, g_xl);
    cudaGetSymbolAddress((void**)&wqh, g_WTqkv_h);
    cudaGetSymbolAddress((void**)&wql, g_WTqkv_l);
    cudaGetSymbolAddress((void**)&woh, g_WTo_h);
    cudaGetSymbolAddress((void**)&wol, g_WTo_l);
    cudaGetSymbolAddress((void**)&oh, g_Oh);
    cudaGetSymbolAddress((void**)&ol, g_Ol);
    cudaGetSymbolAddress((void**)&qkvh, g_QKVh);
    cudaGetSymbolAddress((void**)&qkvl, g_QKVl);
    cudaGetSymbolAddress((void**)&bqkv, g_biasqkv);

    cudaFuncSetAttribute(gemm_bf16s, cudaFuncAttributeMaxDynamicSharedMemorySize,
                         GEMM_SMEM_BYTES);
    cudaFuncSetAttribute(attn_mma, cudaFuncAttributeMaxDynamicSharedMemorySize,
                         ATT_SMEM);

    const int n4 = M_TOTAL * EMB / 4;
    split_f32_bf16<<<(n4 + 255) / 256, 256>>>(x, xh, xl, n4);
    wsplit_t<<<dim3(32, 32), dim3(32, 8)>>>(Wq, wqh, wql);
    wsplit_t<<<dim3(32, 32), dim3(32, 8)>>>(Wk, wqh + (size_t)EMB * EMB, wql + (size_t)EMB * EMB);
    wsplit_t<<<dim3(32, 32), dim3(32, 8)>>>(Wv, wqh + (size_t)2 * EMB * EMB, wql + (size_t)2 * EMB * EMB);
    wsplit_t<<<dim3(32, 32), dim3(32, 8)>>>(Wo, woh, wol);
    concat_bias<<<4, 256>>>(bq, bk, bv, bqkv);

    // QKV projection -> split bf16 QKV
    gemm_bf16s<<<dim3(QKV_LD / GT_N, M_TOTAL / GT_M), 256, GEMM_SMEM_BYTES>>>(
        xh, xl, wqh, wql, bqkv, nullptr, qkvh, qkvl, QKV_LD);

    // tensor-core flash attention -> split bf16 O
    attn_mma<<<dim3(S_LEN / 128, BATCH * NH), 256, ATT_SMEM>>>(qkvh, qkvl, oh, ol);

    // output projection -> fp32 out
    gemm_bf16s<<<dim3(EMB / GT_N, M_TOTAL / GT_M), 256, GEMM_SMEM_BYTES>>>(
        oh, ol, woh, wol, bo, out, nullptr, nullptr, EMB);
}

// round 5
// speedup vs baseline: 3.5328x; 1.1567x over previous
#include <cuda_runtime.h>
#include <cuda_bf16.h>
#include <math.h>
#include <stdint.h>

#define EMB    1024
#define S_LEN  2048
#define BATCH  4
#define NH     16
#define HD     64
#define M_TOTAL (BATCH * S_LEN)   // 8192
#define QKV_LD 3072

__device__ __forceinline__ uint32_t smem_to_u32(const void* p) {
    uint32_t a;
    asm("{ .reg .u64 t; cvta.to.shared.u64 t, %1; cvt.u32.u64 %0, t; }"
        : "=r"(a) : "l"(p));
    return a;
}
__device__ __forceinline__ void cpa16(uint32_t s, const void* g) {
    asm volatile("cp.async.cg.shared.global [%0], [%1], 16;\n" :: "r"(s), "l"(g));
}
__device__ __forceinline__ void ldm_x4(uint32_t& r0, uint32_t& r1, uint32_t& r2,
                                       uint32_t& r3, uint32_t addr) {
    asm volatile("ldmatrix.sync.aligned.m8n8.x4.shared.b16 {%0,%1,%2,%3}, [%4];"
                 : "=r"(r0), "=r"(r1), "=r"(r2), "=r"(r3) : "r"(addr));
}
__device__ __forceinline__ void ldm_x4t(uint32_t& r0, uint32_t& r1, uint32_t& r2,
                                        uint32_t& r3, uint32_t addr) {
    asm volatile("ldmatrix.sync.aligned.m8n8.x4.trans.shared.b16 {%0,%1,%2,%3}, [%4];"
                 : "=r"(r0), "=r"(r1), "=r"(r2), "=r"(r3) : "r"(addr));
}
__device__ __forceinline__ void mma_bf16(float& c0, float& c1, float& c2, float& c3,
                                         uint32_t a0, uint32_t a1, uint32_t a2, uint32_t a3,
                                         uint32_t b0, uint32_t b1) {
    asm volatile("mma.sync.aligned.m16n8k16.row.col.f32.bf16.bf16.f32 "
                 "{%0,%1,%2,%3}, {%4,%5,%6,%7}, {%8,%9}, {%0,%1,%2,%3};"
                 : "+f"(c0), "+f"(c1), "+f"(c2), "+f"(c3)
                 : "r"(a0), "r"(a1), "r"(a2), "r"(a3), "r"(b0), "r"(b1));
}
__device__ __forceinline__ float ex2f(float x) {
    float r; asm("ex2.approx.f32 %0, %1;" : "=f"(r) : "f"(x)); return r;
}
// split v into hi (truncated bf16) + lo; return packed hi pair + lo floats
__device__ __forceinline__ void split2_pack(float v0, float v1, uint32_t& hpack,
                                            float& l0, float& l1) {
    uint32_t u0 = __float_as_uint(v0), u1 = __float_as_uint(v1);
    hpack = (u1 & 0xFFFF0000u) | (u0 >> 16);
    l0 = v0 - __uint_as_float(u0 & 0xFFFF0000u);
    l1 = v1 - __uint_as_float(u1 & 0xFFFF0000u);
}

// ======================= scratch globals ====================================
__device__ __nv_bfloat16 g_xh[(size_t)M_TOTAL * EMB];
__device__ __nv_bfloat16 g_xl[(size_t)M_TOTAL * EMB];
__device__ __nv_bfloat16 g_WTqkv_h[(size_t)QKV_LD * EMB];
__device__ __nv_bfloat16 g_WTqkv_l[(size_t)QKV_LD * EMB];
__device__ __nv_bfloat16 g_WTo_h[(size_t)EMB * EMB];
__device__ __nv_bfloat16 g_WTo_l[(size_t)EMB * EMB];
__device__ float g_biasqkv[QKV_LD];
__device__ __nv_bfloat16 g_QKVh[(size_t)M_TOTAL * QKV_LD];
__device__ __nv_bfloat16 g_QKVl[(size_t)M_TOTAL * QKV_LD];
__device__ __nv_bfloat16 g_Oh[(size_t)M_TOTAL * EMB];
__device__ __nv_bfloat16 g_Ol[(size_t)M_TOTAL * EMB];

// ======================= conversion kernels =================================
__global__ void split_f32_bf16(const float* __restrict__ in,
                               __nv_bfloat16* __restrict__ hi,
                               __nv_bfloat16* __restrict__ lo, int n4) {
    int i = blockIdx.x * blockDim.x + threadIdx.x;
    if (i >= n4) return;
    float4 v = ((const float4*)in)[i];
    __nv_bfloat16 ha = __float2bfloat16_rn(v.x);
    __nv_bfloat16 hb = __float2bfloat16_rn(v.y);
    __nv_bfloat16 hc = __float2bfloat16_rn(v.z);
    __nv_bfloat16 hd = __float2bfloat16_rn(v.w);
    __nv_bfloat16 la = __float2bfloat16_rn(v.x - __bfloat162float(ha));
    __nv_bfloat16 lb = __float2bfloat16_rn(v.y - __bfloat162float(hb));
    __nv_bfloat16 lc = __float2bfloat16_rn(v.z - __bfloat162float(hc));
    __nv_bfloat16 ld = __float2bfloat16_rn(v.w - __bfloat162float(hd));
    __nv_bfloat162* H = (__nv_bfloat162*)hi;
    __nv_bfloat162* L = (__nv_bfloat162*)lo;
    H[2 * i]     = __nv_bfloat162(ha, hb);
    H[2 * i + 1] = __nv_bfloat162(hc, hd);
    L[2 * i]     = __nv_bfloat162(la, lb);
    L[2 * i + 1] = __nv_bfloat162(lc, ld);
}

__global__ void wsplit_t(const float* __restrict__ W,
                         __nv_bfloat16* __restrict__ WTh,
                         __nv_bfloat16* __restrict__ WTl) {
    __shared__ float t[32][33];
    const int n0 = blockIdx.x * 32, k0 = blockIdx.y * 32;
    const int tx = threadIdx.x, ty = threadIdx.y;
    #pragma unroll
    for (int r = 0; r < 32; r += 8)
        t[ty + r][tx] = W[(size_t)(k0 + ty + r) * EMB + n0 + tx];
    __syncthreads();
    #pragma unroll
    for (int r = 0; r < 32; r += 8) {
        float v = t[tx][ty + r];
        __nv_bfloat16 h = __float2bfloat16_rn(v);
        __nv_bfloat16 l = __float2bfloat16_rn(v - __bfloat162float(h));
        WTh[(size_t)(n0 + ty + r) * EMB + k0 + tx] = h;
        WTl[(size_t)(n0 + ty + r) * EMB + k0 + tx] = l;
    }
}

__global__ void concat_bias(const float* __restrict__ bq, const float* __restrict__ bk,
                            const float* __restrict__ bv, float* __restrict__ o) {
    int i = blockIdx.x * blockDim.x + threadIdx.x;
    if (i < EMB) { o[i] = bq[i]; o[EMB + i] = bk[i]; o[2 * EMB + i] = bv[i]; }
}

// ======================= mma.sync split-bf16 GEMM ===========================
#define GT_M 128
#define GT_N 128
#define KCH  64
#define NCH  48
#define STAGE_BYTES (2 * GT_M * 128)
#define GEMM_SMEM_BYTES (3 * STAGE_BYTES)

__global__ __launch_bounds__(256, 2)
void gemm_bf16s(const __nv_bfloat16* __restrict__ Ah, const __nv_bfloat16* __restrict__ Al,
                const __nv_bfloat16* __restrict__ Bh, const __nv_bfloat16* __restrict__ Bl,
                const float* __restrict__ bias,
                float* __restrict__ Cf,                 // fp32 out (or null)
                __nv_bfloat16* __restrict__ Ch,         // split bf16 out
                __nv_bfloat16* __restrict__ Cl,
                int ldC) {
    extern __shared__ char smem[];
    const uint32_t sb = smem_to_u32(smem);
    const int tid  = threadIdx.x;
    const int wid  = tid >> 5;
    const int lane = tid & 31;
    const int wm = wid & 1;
    const int wn = wid >> 1;
    const int m0 = blockIdx.y * GT_M;
    const int n0 = blockIdx.x * GT_N;

    const __nv_bfloat16* Ap[3] = {Ah, Al, Ah};
    const __nv_bfloat16* Bp[3] = {Bh, Bh, Bl};

    auto load_chunk = [&](int ci) {
        const int pass = ci >> 4, kc = ci & 15;
        const __nv_bfloat16* A = Ap[pass];
        const __nv_bfloat16* B = Bp[pass];
        const uint32_t ab = sb + (ci % 3) * STAGE_BYTES;
        const uint32_t bb = ab + GT_M * 128;
        #pragma unroll
        for (int j = 0; j < 4; ++j) {
            const int idx = tid + j * 256;
            const int row = idx >> 3, g = idx & 7;
            const uint32_t off = row * 128 + ((g * 16) ^ ((row & 7) << 4));
            cpa16(ab + off, A + (size_t)(m0 + row) * EMB + kc * KCH + g * 8);
        }
        #pragma unroll
        for (int j = 0; j < 4; ++j) {
            const int idx = tid + j * 256;
            const int row = idx >> 3, g = idx & 7;
            const uint32_t off = row * 128 + ((g * 16) ^ ((row & 7) << 4));
            cpa16(bb + off, B + (size_t)(n0 + row) * EMB + kc * KCH + g * 8);
        }
        asm volatile("cp.async.commit_group;\n" ::: "memory");
    };

    float acc[4][4][4];
    #pragma unroll
    for (int mt = 0; mt < 4; ++mt)
        #pragma unroll
        for (int nt = 0; nt < 4; ++nt)
            #pragma unroll
            for (int r = 0; r < 4; ++r) acc[mt][nt][r] = 0.0f;

    const int arow_l  = wm * 64 + (lane & 15);
    const int akb_l   = (lane >> 4) * 16;
    const int asx     = (arow_l & 7) << 4;
    const int brow_l  = wn * 32 + (lane & 7) + ((lane >> 4) & 1) * 8;
    const int bkb_l   = ((lane >> 3) & 1) * 16;
    const int bsx     = (brow_l & 7) << 4;

    load_chunk(0);
    load_chunk(1);

    for (int i = 0; i < NCH; ++i) {
        if (i + 1 < NCH) asm volatile("cp.async.wait_group 1;\n" ::: "memory");
        else             asm volatile("cp.async.wait_group 0;\n" ::: "memory");
        __syncthreads();

        if (i + 2 < NCH) load_chunk(i + 2);

        const uint32_t ab = sb + (i % 3) * STAGE_BYTES;
        const uint32_t bb = ab + GT_M * 128;

        #pragma unroll
        for (int k16 = 0; k16 < 4; ++k16) {
            const int kb = k16 * 32;
            uint32_t a[4][4];
            #pragma unroll
            for (int mt = 0; mt < 4; ++mt) {
                const int row = arow_l + mt * 16;
                ldm_x4(a[mt][0], a[mt][1], a[mt][2], a[mt][3],
                       ab + row * 128 + ((kb + akb_l) ^ asx));
            }
            uint32_t b[4][2];
            #pragma unroll
            for (int nt2 = 0; nt2 < 2; ++nt2) {
                const int row = brow_l + nt2 * 16;
                uint32_t r0, r1, r2, r3;
                ldm_x4(r0, r1, r2, r3, bb + row * 128 + ((kb + bkb_l) ^ bsx));
                b[nt2 * 2][0] = r0; b[nt2 * 2][1] = r1;
                b[nt2 * 2 + 1][0] = r2; b[nt2 * 2 + 1][1] = r3;
            }
            #pragma unroll
            for (int mt = 0; mt < 4; ++mt)
                #pragma unroll
                for (int nt = 0; nt < 4; ++nt)
                    mma_bf16(acc[mt][nt][0], acc[mt][nt][1], acc[mt][nt][2], acc[mt][nt][3],
                             a[mt][0], a[mt][1], a[mt][2], a[mt][3],
                             b[nt][0], b[nt][1]);
        }
    }

    const int rbase = m0 + wm * 64 + (lane >> 2);
    const int cbase = n0 + wn * 32 + (lane & 3) * 2;
    if (Cf) {
        #pragma unroll
        for (int mt = 0; mt < 4; ++mt) {
            #pragma unroll
            for (int nt = 0; nt < 4; ++nt) {
                const int c = cbase + nt * 8;
                const float b0 = bias[c], b1 = bias[c + 1];
                float2 v0, v1;
                v0.x = acc[mt][nt][0] + b0; v0.y = acc[mt][nt][1] + b1;
                v1.x = acc[mt][nt][2] + b0; v1.y = acc[mt][nt][3] + b1;
                *(float2*)&Cf[(size_t)(rbase + mt * 16) * ldC + c] = v0;
                *(float2*)&Cf[(size_t)(rbase + mt * 16 + 8) * ldC + c] = v1;
            }
        }
    } else {
        #pragma unroll
        for (int mt = 0; mt < 4; ++mt) {
            #pragma unroll
            for (int nt = 0; nt < 4; ++nt) {
                const int c = cbase + nt * 8;
                const float b0 = bias[c], b1 = bias[c + 1];
                float v0 = acc[mt][nt][0] + b0, v1 = acc[mt][nt][1] + b1;
                float v2 = acc[mt][nt][2] + b0, v3 = acc[mt][nt][3] + b1;
                uint32_t h01, h23; float l0, l1, l2, l3;
                split2_pack(v0, v1, h01, l0, l1);
                split2_pack(v2, v3, h23, l2, l3);
                __nv_bfloat162 lp01 = __floats2bfloat162_rn(l0, l1);
                __nv_bfloat162 lp23 = __floats2bfloat162_rn(l2, l3);
                const size_t o0 = (size_t)(rbase + mt * 16) * ldC + c;
                const size_t o1 = (size_t)(rbase + mt * 16 + 8) * ldC + c;
                *(uint32_t*)(Ch + o0) = h01;
                *(uint32_t*)(Cl + o0) = *(uint32_t*)&lp01;
                *(uint32_t*)(Ch + o1) = h23;
                *(uint32_t*)(Cl + o1) = *(uint32_t*)&lp23;
            }
        }
    }
}

// ======================= tensor-core flash attention ========================
// CTA: 128 q-rows x full flash loop over 32 kv-tiles of 64.
// 8 warps, each owns 16 q-rows. smem 96KB; 2 CTAs/SM co-resident.
#define ATT_SMEM 98304

__global__ __launch_bounds__(256, 2)
void attn_mma(const __nv_bfloat16* __restrict__ QKVh,
              const __nv_bfloat16* __restrict__ QKVl,
              __nv_bfloat16* __restrict__ Oh,
              __nv_bfloat16* __restrict__ Ol) {
    extern __shared__ char smem[];
    const uint32_t sb  = smem_to_u32(smem);
    const uint32_t sQh = sb;
    const uint32_t sQl = sb + 16384;
    const uint32_t sKV = sb + 32768;

    const int tid = threadIdx.x, wid = tid >> 5, lane = tid & 31;
    const int bh = blockIdx.y;
    const int b = bh >> 4, h = bh & 15;
    const int qbase = blockIdx.x * 128;
    const size_t rowbase = (size_t)b * S_LEN;

    const __nv_bfloat16* qh_g = QKVh + rowbase * QKV_LD + h * HD;
    const __nv_bfloat16* ql_g = QKVl + rowbase * QKV_LD + h * HD;
    const __nv_bfloat16* kh_g = qh_g + EMB;
    const __nv_bfloat16* kl_g = ql_g + EMB;
    const __nv_bfloat16* vh_g = qh_g + 2 * EMB;
    const __nv_bfloat16* vl_g = ql_g + 2 * EMB;

    auto ldKV = [&](int t) {
        const uint32_t base = sKV + (t & 1) * 32768;
        #pragma unroll
        for (int j = 0; j < 2; ++j) {
            const int idx = tid + j * 256;
            const int row = idx >> 3, g = idx & 7;
            const uint32_t off = row * 128 + ((g * 16) ^ ((row & 7) << 4));
            const size_t gofs = (size_t)(t * 64 + row) * QKV_LD + g * 8;
            cpa16(base + off,         kh_g + gofs);
            cpa16(base + 8192 + off,  kl_g + gofs);
            cpa16(base + 16384 + off, vh_g + gofs);
            cpa16(base + 24576 + off, vl_g + gofs);
        }
        asm volatile("cp.async.commit_group;\n" ::: "memory");
    };

    // Q tile load (group 0, committed with KV0)
    #pragma unroll
    for (int j = 0; j < 4; ++j) {
        const int idx = tid + j * 256;
        const int row = idx >> 3, g = idx & 7;
        const uint32_t off = row * 128 + ((g * 16) ^ ((row & 7) << 4));
        const size_t gofs = (size_t)(qbase + row) * QKV_LD + g * 8;
        cpa16(sQh + off, qh_g + gofs);
        cpa16(sQl + off, ql_g + gofs);
    }
    ldKV(0);
    ldKV(1);

    // fragment address components
    const int wr    = wid * 16;
    const int q_row = wr + (lane & 7) + ((lane >> 3) & 1) * 8;
    const int q_sx  = (q_row & 7) << 4;
    const int q_cb  = ((lane >> 4) & 1) * 16;           // bytes (+8 cols)
    const int k_rl  = (lane & 7) + ((lane >> 4) & 1) * 8;
    const int k_cb  = ((lane >> 3) & 1) * 16;
    const int v_rl  = (lane & 7) + ((lane >> 3) & 1) * 8;
    const int v_cb  = ((lane >> 4) & 1) * 16;

    float m0v = -INFINITY, m1v = -INFINITY, l0s = 0.0f, l1s = 0.0f;
    float acc[8][4];
    #pragma unroll
    for (int e = 0; e < 8; ++e)
        #pragma unroll
        for (int r = 0; r < 4; ++r) acc[e][r] = 0.0f;

    const float cs = 0.125f * 1.4426950408889634f;   // scale * log2(e)
    const int NT = S_LEN / 64;

    for (int t = 0; t < NT; ++t) {
        if (t + 1 < NT) asm volatile("cp.async.wait_group 1;\n" ::: "memory");
        else            asm volatile("cp.async.wait_group 0;\n" ::: "memory");
        __syncthreads();

        const uint32_t kb  = sKV + (t & 1) * 32768;
        const uint32_t klb = kb + 8192;
        const uint32_t vhb = kb + 16384;
        const uint32_t vlb = kb + 24576;

        // ---- S = Q K^T (3-pass split), fp32 accum in C-frag layout
        float s[8][4];
        #pragma unroll
        for (int e = 0; e < 8; ++e)
            #pragma unroll
            for (int r = 0; r < 4; ++r) s[e][r] = 0.0f;

        #pragma unroll
        for (int kd = 0; kd < 4; ++kd) {
            const uint32_t qoff = q_row * 128 + ((kd * 32 + q_cb) ^ q_sx);
            uint32_t qh[4], ql[4];
            ldm_x4(qh[0], qh[1], qh[2], qh[3], sQh + qoff);
            ldm_x4(ql[0], ql[1], ql[2], ql[3], sQl + qoff);
            #pragma unroll
            for (int e = 0; e < 4; ++e) {
                const int krow = e * 16 + k_rl;
                const uint32_t koff = krow * 128 + ((kd * 32 + k_cb) ^ ((krow & 7) << 4));
                uint32_t h0, h1, h2, h3, g0, g1, g2, g3;
                ldm_x4(h0, h1, h2, h3, kb + koff);
                ldm_x4(g0, g1, g2, g3, klb + koff);
                mma_bf16(s[2*e][0], s[2*e][1], s[2*e][2], s[2*e][3],
                         qh[0], qh[1], qh[2], qh[3], h0, h1);
                mma_bf16(s[2*e][0], s[2*e][1], s[2*e][2], s[2*e][3],
                         ql[0], ql[1], ql[2], ql[3], h0, h1);
                mma_bf16(s[2*e][0], s[2*e][1], s[2*e][2], s[2*e][3],
                         qh[0], qh[1], qh[2], qh[3], g0, g1);
                mma_bf16(s[2*e+1][0], s[2*e+1][1], s[2*e+1][2], s[2*e+1][3],
                         qh[0], qh[1], qh[2], qh[3], h2, h3);
                mma_bf16(s[2*e+1][0], s[2*e+1][1], s[2*e+1][2], s[2*e+1][3],
                         ql[0], ql[1], ql[2], ql[3], h2, h3);
                mma_bf16(s[2*e+1][0], s[2*e+1][1], s[2*e+1][2], s[2*e+1][3],
                         qh[0], qh[1], qh[2], qh[3], g2, g3);
            }
        }

        // ---- online softmax (base-2 domain); rows r (c0,c1) and r+8 (c2,c3)
        float r0m = -INFINITY, r1m = -INFINITY;
        #pragma unroll
        for (int e = 0; e < 8; ++e) {
            r0m = fmaxf(r0m, fmaxf(s[e][0], s[e][1]));
            r1m = fmaxf(r1m, fmaxf(s[e][2], s[e][3]));
        }
        r0m = fmaxf(r0m, __shfl_xor_sync(0xffffffffu, r0m, 1));
        r0m = fmaxf(r0m, __shfl_xor_sync(0xffffffffu, r0m, 2));
        r1m = fmaxf(r1m, __shfl_xor_sync(0xffffffffu, r1m, 1));
        r1m = fmaxf(r1m, __shfl_xor_sync(0xffffffffu, r1m, 2));

        const float mn0 = fmaxf(m0v, r0m * cs);
        const float mn1 = fmaxf(m1v, r1m * cs);
        const float cor0 = ex2f(m0v - mn0);
        const float cor1 = ex2f(m1v - mn1);
        m0v = mn0; m1v = mn1;

        float rs0 = 0.0f, rs1 = 0.0f;
        #pragma unroll
        for (int e = 0; e < 8; ++e) {
            s[e][0] = ex2f(fmaf(s[e][0], cs, -mn0)); rs0 += s[e][0];
            s[e][1] = ex2f(fmaf(s[e][1], cs, -mn0)); rs0 += s[e][1];
            s[e][2] = ex2f(fmaf(s[e][2], cs, -mn1)); rs1 += s[e][2];
            s[e][3] = ex2f(fmaf(s[e][3], cs, -mn1)); rs1 += s[e][3];
        }
        rs0 += __shfl_xor_sync(0xffffffffu, rs0, 1);
        rs0 += __shfl_xor_sync(0xffffffffu, rs0, 2);
        rs1 += __shfl_xor_sync(0xffffffffu, rs1, 1);
        rs1 += __shfl_xor_sync(0xffffffffu, rs1, 2);
        l0s = l0s * cor0 + rs0;
        l1s = l1s * cor1 + rs1;
        #pragma unroll
        for (int e = 0; e < 8; ++e) {
            acc[e][0] *= cor0; acc[e][1] *= cor0;
            acc[e][2] *= cor1; acc[e][3] *= cor1;
        }

        // ---- O += P V (3-pass split); P lives in registers
        #pragma unroll
        for (int j = 0; j < 4; ++j) {
            uint32_t aph[4], apl[4];
            {
                float la, lb;
                split2_pack(s[2*j][0],   s[2*j][1],   aph[0], la, lb);
                __nv_bfloat162 p = __floats2bfloat162_rn(la, lb);
                apl[0] = *(uint32_t*)&p;
                split2_pack(s[2*j][2],   s[2*j][3],   aph[1], la, lb);
                p = __floats2bfloat162_rn(la, lb); apl[1] = *(uint32_t*)&p;
                split2_pack(s[2*j+1][0], s[2*j+1][1], aph[2], la, lb);
                p = __floats2bfloat162_rn(la, lb); apl[2] = *(uint32_t*)&p;
                split2_pack(s[2*j+1][2], s[2*j+1][3], aph[3], la, lb);
                p = __floats2bfloat162_rn(la, lb); apl[3] = *(uint32_t*)&p;
            }
            #pragma unroll
            for (int e = 0; e < 4; ++e) {
                const int vrow = j * 16 + v_rl;
                const uint32_t voff = vrow * 128 + ((e * 32 + v_cb) ^ ((vrow & 7) << 4));
                uint32_t h0, h1, h2, h3, g0, g1, g2, g3;
                ldm_x4t(h0, h1, h2, h3, vhb + voff);
                ldm_x4t(g0, g1, g2, g3, vlb + voff);
                mma_bf16(acc[2*e][0], acc[2*e][1], acc[2*e][2], acc[2*e][3],
                         aph[0], aph[1], aph[2], aph[3], h0, h1);
                mma_bf16(acc[2*e][0], acc[2*e][1], acc[2*e][2], acc[2*e][3],
                         apl[0], apl[1], apl[2], apl[3], h0, h1);
                mma_bf16(acc[2*e][0], acc[2*e][1], acc[2*e][2], acc[2*e][3],
                         aph[0], aph[1], aph[2], aph[3], g0, g1);
                mma_bf16(acc[2*e+1][0], acc[2*e+1][1], acc[2*e+1][2], acc[2*e+1][3],
                         aph[0], aph[1], aph[2], aph[3], h2, h3);
                mma_bf16(acc[2*e+1][0], acc[2*e+1][1], acc[2*e+1][2], acc[2*e+1][3],
                         apl[0], apl[1], apl[2], apl[3], h2, h3);
                mma_bf16(acc[2*e+1][0], acc[2*e+1][1], acc[2*e+1][2], acc[2*e+1][3],
                         aph[0], aph[1], aph[2], aph[3], g2, g3);
            }
        }

        __syncthreads();
        if (t + 2 < NT) ldKV(t + 2);
    }

    // ---- epilogue: normalize, split, store bf16 hi/lo
    const float inv0 = 1.0f / l0s;
    const float inv1 = 1.0f / l1s;
    const size_t row0 = rowbase + qbase + wr + (lane >> 2);
    const size_t row1 = row0 + 8;
    const int cb = h * HD + 2 * (lane & 3);
    #pragma unroll
    for (int e = 0; e < 8; ++e) {
        const int c = cb + e * 8;
        float v0 = acc[e][0] * inv0, v1 = acc[e][1] * inv0;
        float v2 = acc[e][2] * inv1, v3 = acc[e][3] * inv1;
        uint32_t h01, h23; float l0, l1, l2, l3;
        split2_pack(v0, v1, h01, l0, l1);
        split2_pack(v2, v3, h23, l2, l3);
        __nv_bfloat162 lp01 = __floats2bfloat162_rn(l0, l1);
        __nv_bfloat162 lp23 = __floats2bfloat162_rn(l2, l3);
        *(uint32_t*)(Oh + row0 * EMB + c) = h01;
        *(uint32_t*)(Ol + row0 * EMB + c) = *(uint32_t*)&lp01;
        *(uint32_t*)(Oh + row1 * EMB + c) = h23;
        *(uint32_t*)(Ol + row1 * EMB + c) = *(uint32_t*)&lp23;
    }
}

// ======================= launch =============================================
extern "C" void kernel_launch(void* const* d_in, const int* in_sizes, int n_in,
                              void* d_out, int out_size) {
    const float* x  = (const float*)d_in[0];
    const float* Wq = (const float*)d_in[1];
    const float* bq = (const float*)d_in[2];
    const float* Wk = (const float*)d_in[3];
    const float* bk = (const float*)d_in[4];
    const float* Wv = (const float*)d_in[5];
    const float* bv = (const float*)d_in[6];
    const float* Wo = (const float*)d_in[7];
    const float* bo = (const float*)d_in[8];
    float* out = (float*)d_out;

    __nv_bfloat16 *xh, *xl, *wqh, *wql, *woh, *wol, *oh, *ol, *qkvh, *qkvl;
    float *bqkv;
    cudaGetSymbolAddress((void**)&xh, g_xh);
    cudaGetSymbolAddress((void**)&xl, g_xl);
    cudaGetSymbolAddress((void**)&wqh, g_WTqkv_h);
    cudaGetSymbolAddress((void**)&wql, g_WTqkv_l);
    cudaGetSymbolAddress((void**)&woh, g_WTo_h);
    cudaGetSymbolAddress((void**)&wol, g_WTo_l);
    cudaGetSymbolAddress((void**)&oh, g_Oh);
    cudaGetSymbolAddress((void**)&ol, g_Ol);
    cudaGetSymbolAddress((void**)&qkvh, g_QKVh);
    cudaGetSymbolAddress((void**)&qkvl, g_QKVl);
    cudaGetSymbolAddress((void**)&bqkv, g_biasqkv);

    cudaFuncSetAttribute(gemm_bf16s, cudaFuncAttributeMaxDynamicSharedMemorySize,
                         GEMM_SMEM_BYTES);
    cudaFuncSetAttribute(attn_mma, cudaFuncAttributeMaxDynamicSharedMemorySize,
                         ATT_SMEM);

    const int n4 = M_TOTAL * EMB / 4;
    split_f32_bf16<<<(n4 + 255) / 256, 256>>>(x, xh, xl, n4);
    wsplit_t<<<dim3(32, 32), dim3(32, 8)>>>(Wq, wqh, wql);
    wsplit_t<<<dim3(32, 32), dim3(32, 8)>>>(Wk, wqh + (size_t)EMB * EMB, wql + (size_t)EMB * EMB);
    wsplit_t<<<dim3(32, 32), dim3(32, 8)>>>(Wv, wqh + (size_t)2 * EMB * EMB, wql + (size_t)2 * EMB * EMB);
    wsplit_t<<<dim3(32, 32), dim3(32, 8)>>>(Wo, woh, wol);
    concat_bias<<<4, 256>>>(bq, bk, bv, bqkv);

    // QKV projection -> split bf16 QKV
    gemm_bf16s<<<dim3(QKV_LD / GT_N, M_TOTAL / GT_M), 256, GEMM_SMEM_BYTES>>>(
        xh, xl, wqh, wql, bqkv, nullptr, qkvh, qkvl, QKV_LD);

    // tensor-core flash attention -> split bf16 O
    attn_mma<<<dim3(S_LEN / 128, BATCH * NH), 256, ATT_SMEM>>>(qkvh, qkvl, oh, ol);

    // output projection -> fp32 out
    gemm_bf16s<<<dim3(EMB / GT_N, M_TOTAL / GT_M), 256, GEMM_SMEM_BYTES>>>(
        oh, ol, woh, wol, bo, out, nullptr, nullptr, EMB);
}